// round 2
// baseline (speedup 1.0000x reference)
#include <cuda_runtime.h>
#include <math.h>

#define NB_LSTM 128

// ---------------- device scratch (statics; no cudaMalloc allowed) ----------
__device__ float g_trel[500 * 100];          // tanh(rel_emb)
__device__ float g_tin[8192 * 500];          // lstm input  [token][500]
__device__ float g_xp[8192 * 1024];          // x@w_ih^T + b_ih + b_hh
__device__ float g_outseq[8192 * 256];       // masked hidden states [b*128+s][256]
__device__ float g_h[2][64 * 256];           // double-buffered h
__device__ unsigned g_bar_count = 0;
__device__ unsigned g_bar_gen = 0;

// ---------------- grid barrier (all NB_LSTM CTAs co-resident) --------------
__device__ __forceinline__ void grid_barrier() {
    __syncthreads();
    if (threadIdx.x == 0) {
        __threadfence();
        unsigned gen = __ldcg(&g_bar_gen);
        unsigned arrived = atomicAdd(&g_bar_count, 1u);
        if (arrived == (unsigned)(NB_LSTM - 1)) {
            g_bar_count = 0;
            __threadfence();
            atomicAdd(&g_bar_gen, 1u);
        } else {
            while (__ldcg(&g_bar_gen) == gen) { }
        }
    }
    __syncthreads();
}

// ============================================================================
// K0: precompute tanh(rel_emb)
// ============================================================================
__global__ void k_tanh_rel(const float* __restrict__ rel) {
    int i = blockIdx.x * 256 + threadIdx.x;
    if (i < 500 * 100) g_trel[i] = tanhf(rel[i]);
}

// ============================================================================
// K1: per-token graph attention -> t_input = [word_emb(300) | graph_embed(200)]
// one CTA per token, 256 threads
// smem: sW[100][201] + sHT[32][201] + sRT[32][100] + sE[32]  = 119056 B
// ============================================================================
__global__ void __launch_bounds__(256, 1)
k_token(const int* __restrict__ inputs, const int* __restrict__ triples,
        const int* __restrict__ id2, const float* __restrict__ word_emb,
        const float* __restrict__ ent_emb, const float* __restrict__ W_ent)
{
    extern __shared__ float sm[];
    float* sW  = sm;               // 100 * 201
    float* sHT = sm + 20100;       // 32 * 201
    float* sRT = sm + 26532;       // 32 * 100
    float* sE  = sm + 29732;       // 32
    __shared__ int sIdx[96];
    __shared__ int sValid;

    const int tid = threadIdx.x;
    const int token = blockIdx.x;

    for (int i = tid; i < 20000; i += 256) {
        int d = i / 200, k = i - d * 200;
        sW[d * 201 + k] = W_ent[i];
    }
    if (tid < 96) sIdx[tid] = triples[token * 96 + tid];
    if (tid < 32) sE[tid] = 0.f;
    __syncthreads();

    if (tid < 32) {
        unsigned m = __ballot_sync(0xffffffffu, id2[token * 32 + tid] != -1);
        if (tid == 0) sValid = (m != 0u);
    }
    for (int i = tid; i < 6400; i += 256) {          // head_tail [32][200]
        int t = i / 200, k = i - t * 200;
        int ent = (k < 100) ? sIdx[t * 3 + 0] : sIdx[t * 3 + 1];
        int kk  = (k < 100) ? k : (k - 100);
        sHT[t * 201 + k] = ent_emb[(size_t)ent * 100 + kk];
    }
    for (int i = tid; i < 3200; i += 256) {          // tanh(rel) [32][100]
        int t = i / 100, d = i - t * 100;
        sRT[i] = g_trel[sIdx[t * 3 + 2] * 100 + d];
    }
    __syncthreads();

    // e[t] = sum_d tanh( HT[t,:] . W_ent[d,:] ) * trel[t,d]
    if (tid < 200) {
        const int tt = tid / 25;          // 0..7
        const int dd = tid - tt * 25;     // 0..24
        const float* pa = sHT + tt * 201;
        const float* pb = sW  + dd * 201;
        float acc[4][4];
        #pragma unroll
        for (int i = 0; i < 4; i++)
            #pragma unroll
            for (int j = 0; j < 4; j++) acc[i][j] = 0.f;

        for (int k = 0; k < 200; k++) {
            float a0 = pa[k];
            float a1 = pa[ 8 * 201 + k];
            float a2 = pa[16 * 201 + k];
            float a3 = pa[24 * 201 + k];
            float b0 = pb[k];
            float b1 = pb[25 * 201 + k];
            float b2 = pb[50 * 201 + k];
            float b3 = pb[75 * 201 + k];
            acc[0][0] += a0*b0; acc[0][1] += a0*b1; acc[0][2] += a0*b2; acc[0][3] += a0*b3;
            acc[1][0] += a1*b0; acc[1][1] += a1*b1; acc[1][2] += a1*b2; acc[1][3] += a1*b3;
            acc[2][0] += a2*b0; acc[2][1] += a2*b1; acc[2][2] += a2*b2; acc[2][3] += a2*b3;
            acc[3][0] += a3*b0; acc[3][1] += a3*b1; acc[3][2] += a3*b2; acc[3][3] += a3*b3;
        }
        #pragma unroll
        for (int i = 0; i < 4; i++) {
            int t = tt + 8 * i;
            float contrib = 0.f;
            #pragma unroll
            for (int j = 0; j < 4; j++)
                contrib += tanhf(acc[i][j]) * sRT[t * 100 + dd + 25 * j];
            atomicAdd(&sE[t], contrib);
        }
    }
    __syncthreads();

    if (tid < 32) {                                  // softmax over 32 triples
        float v = sE[tid];
        float m = v;
        #pragma unroll
        for (int o = 16; o; o >>= 1) m = fmaxf(m, __shfl_xor_sync(0xffffffffu, m, o));
        float e = expf(v - m);
        float z = e;
        #pragma unroll
        for (int o = 16; o; o >>= 1) z += __shfl_xor_sync(0xffffffffu, z, o);
        sE[tid] = e / z;                             // alpha
    }
    __syncthreads();

    const int widx = inputs[token];
    for (int j = tid; j < 300; j += 256)
        g_tin[(size_t)token * 500 + j] = word_emb[(size_t)widx * 300 + j];
    if (tid < 200) {
        float ge = 0.f;
        #pragma unroll 8
        for (int t = 0; t < 32; t++) ge += sE[t] * sHT[t * 201 + tid];
        g_tin[(size_t)token * 500 + 300 + tid] = sValid ? ge : 0.f;
    }
}

// ============================================================================
// K2: g_xp[8192,1024] = g_tin[8192,500] @ w_ih^T + (b_ih + b_hh)
// 64x64x16 tiles, 4x4 thread tiles, 256 threads
// ============================================================================
__global__ void __launch_bounds__(256)
k_gemm_x(const float* __restrict__ wih, const float* __restrict__ bih,
         const float* __restrict__ bhh)
{
    __shared__ float As[16 * 68];
    __shared__ float Bs[16 * 68];
    const int tid = threadIdx.x;
    const int n0 = blockIdx.x * 64;
    const int m0 = blockIdx.y * 64;
    const int lm = tid >> 2;            // 0..63
    const int lk = (tid & 3) * 4;       // 0,4,8,12
    const int ty = tid >> 4;            // 0..15 (m sub-tile)
    const int tx = tid & 15;            // 0..15 (n sub-tile)

    float acc[4][4];
    #pragma unroll
    for (int i = 0; i < 4; i++)
        #pragma unroll
        for (int j = 0; j < 4; j++) acc[i][j] = 0.f;

    const float* arow = g_tin + (size_t)(m0 + lm) * 500;
    const float* brow = wih   + (size_t)(n0 + lm) * 500;

    for (int kt = 0; kt < 32; ++kt) {
        int kb = kt * 16;
        #pragma unroll
        for (int j = 0; j < 4; ++j) {
            int k = kb + lk + j;
            float av = (k < 500) ? arow[k] : 0.f;
            float bv = (k < 500) ? brow[k] : 0.f;
            As[(lk + j) * 68 + lm] = av;
            Bs[(lk + j) * 68 + lm] = bv;
        }
        __syncthreads();
        #pragma unroll
        for (int k = 0; k < 16; ++k) {
            float4 a = *(const float4*)&As[k * 68 + ty * 4];
            float4 b = *(const float4*)&Bs[k * 68 + tx * 4];
            acc[0][0] += a.x*b.x; acc[0][1] += a.x*b.y; acc[0][2] += a.x*b.z; acc[0][3] += a.x*b.w;
            acc[1][0] += a.y*b.x; acc[1][1] += a.y*b.y; acc[1][2] += a.y*b.z; acc[1][3] += a.y*b.w;
            acc[2][0] += a.z*b.x; acc[2][1] += a.z*b.y; acc[2][2] += a.z*b.z; acc[2][3] += a.z*b.w;
            acc[3][0] += a.w*b.x; acc[3][1] += a.w*b.y; acc[3][2] += a.w*b.z; acc[3][3] += a.w*b.w;
        }
        __syncthreads();
    }
    #pragma unroll
    for (int j = 0; j < 4; ++j) {
        int n = n0 + tx * 4 + j;
        float bias = bih[n] + bhh[n];
        #pragma unroll
        for (int i = 0; i < 4; ++i)
            g_xp[(size_t)(m0 + ty * 4 + i) * 1024 + n] = acc[i][j] + bias;
    }
}

// ============================================================================
// K3: persistent LSTM. 128 CTAs x 256 threads, co-resident.
// CTA c owns h-columns {2c, 2c+1}; w_hh slice (8 rows x 256) stays in smem.
// Per step: stage h[64,256] (XOR-swizzled smem), 8-way k-split + shfl reduce.
// smem floats: sW 2048 | sH 16384 | sC 128  -> 74240 B
// ============================================================================
__global__ void __launch_bounds__(256, 1)
k_lstm(const float* __restrict__ whh, const int* __restrict__ lengths)
{
    extern __shared__ float sm[];
    float* sW = sm;            // [8][256]   rows: q*4+g
    float* sH = sm + 2048;     // [64][256]  xor-swizzled within row
    float* sC = sm + 18432;    // [64][2]

    const int tid = threadIdx.x;
    const int cta = blockIdx.x;
    const int hc0 = cta * 2;
    const int ks = tid & 7;              // k-split 0..7
    const int bg = (tid >> 3) & 15;      // batch group (4 batches)
    const int q  = tid >> 7;             // which of the 2 h-cols

    for (int i = tid; i < 2048; i += 256) {
        int r = i >> 8, k = i & 255;
        int qq = r >> 2, g = r & 3;
        sW[i] = whh[(size_t)(g * 256 + hc0 + qq) * 256 + k];
    }
    if (tid < 128) sC[tid] = 0.f;
    if (tid < 128) g_h[0][cta * 128 + tid] = 0.f;
    __threadfence();
    grid_barrier();

    const float* wq = sW + q * 1024;
    const int xk = (bg & 3) * 8;
    int p = 0;

    for (int s = 0; s < 128; ++s) {
        const float* hsrc = g_h[p];
        for (int i = tid; i < 4096; i += 256) {
            float4 v = __ldcg((const float4*)hsrc + i);
            int b = i >> 6;
            int k4 = (i & 63) << 2;
            int kx = k4 ^ (((b >> 2) & 3) * 8);
            *(float4*)&sH[b * 256 + kx] = v;
        }
        __syncthreads();

        float acc[16];
        #pragma unroll
        for (int t = 0; t < 16; ++t) acc[t] = 0.f;

        const float* h0 = sH + (bg * 4 + 0) * 256;
        const float* h1 = sH + (bg * 4 + 1) * 256;
        const float* h2 = sH + (bg * 4 + 2) * 256;
        const float* h3 = sH + (bg * 4 + 3) * 256;

        #pragma unroll 4
        for (int kk = 0; kk < 32; ++kk) {
            int k  = ks + (kk << 3);
            int kx2 = k ^ xk;
            float w0 = wq[k], w1 = wq[256 + k], w2 = wq[512 + k], w3 = wq[768 + k];
            float v0 = h0[kx2], v1 = h1[kx2], v2 = h2[kx2], v3 = h3[kx2];
            acc[ 0] += v0*w0; acc[ 1] += v1*w0; acc[ 2] += v2*w0; acc[ 3] += v3*w0;
            acc[ 4] += v0*w1; acc[ 5] += v1*w1; acc[ 6] += v2*w1; acc[ 7] += v3*w1;
            acc[ 8] += v0*w2; acc[ 9] += v1*w2; acc[10] += v2*w2; acc[11] += v3*w2;
            acc[12] += v0*w3; acc[13] += v1*w3; acc[14] += v2*w3; acc[15] += v3*w3;
        }
        #pragma unroll
        for (int off = 1; off < 8; off <<= 1) {
            #pragma unroll
            for (int t = 0; t < 16; ++t)
                acc[t] += __shfl_xor_sync(0xffffffffu, acc[t], off);
        }

        if (ks == 0) {
            int hc = hc0 + q;
            #pragma unroll
            for (int bi = 0; bi < 4; ++bi) {
                int b = bg * 4 + bi;
                const float* xp = g_xp + (size_t)(b * 128 + s) * 1024;
                float gi = xp[hc]       + acc[0 * 4 + bi];
                float gf = xp[256 + hc] + acc[1 * 4 + bi];
                float gg = xp[512 + hc] + acc[2 * 4 + bi];
                float go = xp[768 + hc] + acc[3 * 4 + bi];
                float si = 1.f / (1.f + expf(-gi));
                float sf = 1.f / (1.f + expf(-gf));
                float so = 1.f / (1.f + expf(-go));
                float cn = sf * sC[b * 2 + q] + si * tanhf(gg);
                sC[b * 2 + q] = cn;
                float hv = so * tanhf(cn);
                g_h[p ^ 1][b * 256 + hc] = hv;
                g_outseq[(size_t)(b * 128 + s) * 256 + hc] = (s < lengths[b]) ? hv : 0.f;
            }
            __threadfence();
        }
        grid_barrier();
        p ^= 1;
    }
}

// ============================================================================
// K4: attention pool + classifier. one CTA per batch row.
// out = [ log_probs (64*3) | p (64*128) ]
// ============================================================================
__global__ void __launch_bounds__(256)
k_final(const float* __restrict__ W_att, const float* __restrict__ b_att,
        const float* __restrict__ W_out, const float* __restrict__ b_out,
        float* __restrict__ out)
{
    __shared__ float sLog[128];
    __shared__ float sP[128];
    __shared__ float sEnc[256];
    __shared__ float sZ[3];
    const int tid = threadIdx.x;
    const int b = blockIdx.x;

    if (tid < 128) {
        const float* o = g_outseq + (size_t)(b * 128 + tid) * 256;
        float a = 0.f;
        for (int h = 0; h < 256; ++h) a += o[h] * W_att[h];
        sLog[tid] = a + b_att[0];
    }
    __syncthreads();

    if (tid == 0) {
        float mx = -INFINITY;
        for (int s = 0; s < 128; ++s) {
            float m = (sLog[s] != 0.f) ? 1.f : 0.f;
            mx = fmaxf(mx, sLog[s] * m);
        }
        float den = 0.f;
        for (int s = 0; s < 128; ++s) {
            float m = (sLog[s] != 0.f) ? 1.f : 0.f;
            den += expf(sLog[s] * m - mx);
        }
        float sum2 = 0.f;
        for (int s = 0; s < 128; ++s) {
            float m = (sLog[s] != 0.f) ? 1.f : 0.f;
            float pv = expf(sLog[s] * m - mx) / den * m;
            sP[s] = pv;
            sum2 += pv;
        }
        float inv = 1.f / (sum2 + 1e-13f);
        for (int s = 0; s < 128; ++s) sP[s] *= inv;
    }
    __syncthreads();

    {
        float a = 0.f;
        const float* base = g_outseq + (size_t)b * 128 * 256 + tid;
        for (int s = 0; s < 128; ++s) a += sP[s] * base[s * 256];
        sEnc[tid] = a;
    }
    __syncthreads();

    if (tid < 3) {
        float z = b_out[tid];
        const float* w = W_out + tid * 256;
        for (int h = 0; h < 256; ++h) z += sEnc[h] * w[h];
        sZ[tid] = z;
    }
    __syncthreads();
    if (tid < 3) {
        float mx = fmaxf(sZ[0], fmaxf(sZ[1], sZ[2]));
        float lse = mx + logf(expf(sZ[0] - mx) + expf(sZ[1] - mx) + expf(sZ[2] - mx));
        out[b * 3 + tid] = sZ[tid] - lse;
    }
    if (tid < 128) out[192 + b * 128 + tid] = sP[tid];
}

// ============================================================================
extern "C" void kernel_launch(void* const* d_in, const int* in_sizes, int n_in,
                              void* d_out, int out_size)
{
    const int*   inputs   = (const int*)d_in[0];
    const int*   triples  = (const int*)d_in[1];
    const int*   lengths  = (const int*)d_in[2];
    const int*   id2      = (const int*)d_in[3];
    const float* word_emb = (const float*)d_in[4];
    const float* ent_emb  = (const float*)d_in[5];
    const float* rel_emb  = (const float*)d_in[6];
    const float* W_ent    = (const float*)d_in[7];
    const float* w_ih     = (const float*)d_in[8];
    const float* w_hh     = (const float*)d_in[9];
    const float* b_ih     = (const float*)d_in[10];
    const float* b_hh     = (const float*)d_in[11];
    const float* W_att    = (const float*)d_in[12];
    const float* b_att    = (const float*)d_in[13];
    const float* W_out    = (const float*)d_in[14];
    const float* b_out    = (const float*)d_in[15];
    float* out = (float*)d_out;

    cudaFuncSetAttribute(k_token, cudaFuncAttributeMaxDynamicSharedMemorySize, 119056);
    cudaFuncSetAttribute(k_lstm,  cudaFuncAttributeMaxDynamicSharedMemorySize, 74240);

    k_tanh_rel<<<(50000 + 255) / 256, 256>>>(rel_emb);
    k_token<<<8192, 256, 119056>>>(inputs, triples, id2, word_emb, ent_emb, W_ent);
    dim3 g2(16, 128);
    k_gemm_x<<<g2, 256>>>(w_ih, b_ih, b_hh);
    k_lstm<<<NB_LSTM, 256, 74240>>>(w_hh, lengths);
    k_final<<<64, 256>>>(W_att, b_att, W_out, b_out, out);
}

// round 3
// speedup vs baseline: 1.5890x; 1.5890x over previous
#include <cuda_runtime.h>
#include <math.h>
#include <stdint.h>

#define NB_LSTM 128

// ---------------- device scratch ----------------
__device__ __align__(16) float g_trel[500 * 100];
__device__ __align__(16) float g_tin[8192 * 500];
__device__ __align__(16) float g_xp[8192 * 1024];
__device__ __align__(16) float g_outseq[8192 * 256];
__device__ __align__(16) float g_h[2][64 * 256];   // layout [hc][b]
__device__ int g_flag[NB_LSTM * 32];                // one cache line per CTA
__device__ unsigned g_bar_count = 0;
__device__ unsigned g_bar_gen = 0;

// ---------------- helpers ----------------
__device__ __forceinline__ unsigned smem_u32(const void* p) {
    return (unsigned)__cvta_generic_to_shared(p);
}
__device__ __forceinline__ void cpa16(unsigned dst, const void* src) {
    asm volatile("cp.async.cg.shared.global [%0], [%1], 16;\n" :: "r"(dst), "l"(src));
}
#define CPA_COMMIT() asm volatile("cp.async.commit_group;\n")
template <int N> __device__ __forceinline__ void cpa_wait() {
    asm volatile("cp.async.wait_group %0;\n" :: "n"(N));
}
__device__ __forceinline__ int ld_acq(const int* p) {
    int v;
    asm volatile("ld.global.acquire.gpu.b32 %0, [%1];" : "=r"(v) : "l"(p));
    return v;
}
__device__ __forceinline__ void st_rel(int* p, int v) {
    asm volatile("st.global.release.gpu.b32 [%0], %1;" :: "l"(p), "r"(v));
}

__device__ __forceinline__ void grid_barrier() {
    __syncthreads();
    if (threadIdx.x == 0) {
        __threadfence();
        unsigned gen = *(volatile unsigned*)&g_bar_gen;
        unsigned arrived = atomicAdd(&g_bar_count, 1u);
        if (arrived == (unsigned)(NB_LSTM - 1)) {
            g_bar_count = 0;
            __threadfence();
            atomicAdd(&g_bar_gen, 1u);
        } else {
            while (*(volatile unsigned*)&g_bar_gen == gen) { }
        }
    }
    __syncthreads();
}

// ============================================================================
// K0: precompute tanh(rel_emb)
// ============================================================================
__global__ void k_tanh_rel(const float* __restrict__ rel) {
    int i = blockIdx.x * 256 + threadIdx.x;
    if (i < 500 * 100) g_trel[i] = tanhf(rel[i]);
}

// ============================================================================
// K1: graph attention. 512 CTAs x 512 threads, 16 tokens per CTA.
// smem floats:
//   sW   [100][204]            @ 0        (20400)
//   sHT  [2][32][204]          @ 20400    (13056)
//   sRT  [2][32][100]          @ 33456    (6400)
//   sE   [32]                  @ 39856
//   sIdx [16*96] ints          @ 39888    (1536)
//   sVal [16] ints             @ 41424
// total 41440 floats = 165760 B
// ============================================================================
#define TOK_SW   0
#define TOK_SHT  20400
#define TOK_SRT  33456
#define TOK_SE   39856
#define TOK_SIDX 39888
#define TOK_SVAL 41424
#define TOK_SMEM (41440 * 4)

__device__ __forceinline__ void tok_stage(float* sm, int buf, int it,
                                          const float* ent_emb) {
    const int* idx = (const int*)(sm + TOK_SIDX) + it * 96;
    float* sHT = sm + TOK_SHT + buf * 32 * 204;
    float* sRT = sm + TOK_SRT + buf * 32 * 100;
    for (int i = threadIdx.x; i < 2400; i += 512) {
        if (i < 1600) {
            int t = i / 50, j = i - t * 50;
            int ent = (j < 25) ? idx[t * 3] : idx[t * 3 + 1];
            int jj = (j < 25) ? j : (j - 25);
            int dstf = t * 204 + ((j < 25) ? (j * 4) : (100 + jj * 4));
            cpa16(smem_u32(sHT + dstf), ent_emb + (size_t)ent * 100 + jj * 4);
        } else {
            int r = i - 1600;
            int t = r / 25, j = r - t * 25;
            int rl = idx[t * 3 + 2];
            cpa16(smem_u32(sRT + t * 100 + j * 4), g_trel + rl * 100 + j * 4);
        }
    }
}

__global__ void __launch_bounds__(512, 1)
k_token(const int* __restrict__ inputs, const int* __restrict__ triples,
        const int* __restrict__ id2, const float* __restrict__ word_emb,
        const float* __restrict__ ent_emb, const float* __restrict__ W_ent)
{
    extern __shared__ float sm[];
    const int tid = threadIdx.x;
    const int tok0 = blockIdx.x * 16;

    // prologue group 0: indices (16 tokens) + W_ent
    for (int i = tid; i < 384; i += 512)
        cpa16(smem_u32(sm + TOK_SIDX) + i * 16, triples + (size_t)tok0 * 96 + i * 4);
    for (int i = tid; i < 5000; i += 512) {
        int d = i / 50, j = i - d * 50;
        cpa16(smem_u32(sm + TOK_SW + d * 204 + j * 4), W_ent + d * 200 + j * 4);
    }
    CPA_COMMIT();
    cpa_wait<0>();
    __syncthreads();

    // per-token valid flags (warp per token)
    {
        int it = tid >> 5, lane = tid & 31;
        int v = id2[(size_t)(tok0 + it) * 32 + lane];
        unsigned m = __ballot_sync(0xffffffffu, v != -1);
        if (lane == 0) ((int*)(sm + TOK_SVAL))[it] = (m != 0u);
    }

    tok_stage(sm, 0, 0, ent_emb);
    CPA_COMMIT();

    const int tt = tid & 7;          // 0..7  -> t rows {tt, tt+8, tt+16, tt+24}
    const int dd = tid >> 3;         // 0..49 -> d cols {dd, dd+50}

    for (int it = 0; it < 16; ++it) {
        const int buf = it & 1;
        if (it < 15) {
            tok_stage(sm, buf ^ 1, it + 1, ent_emb);
            CPA_COMMIT();
            cpa_wait<1>();
        } else {
            cpa_wait<0>();
        }
        if (tid < 32) sm[TOK_SE + tid] = 0.f;
        __syncthreads();

        const float* sHT = sm + TOK_SHT + buf * 32 * 204;
        const float* sRT = sm + TOK_SRT + buf * 32 * 100;

        if (tid < 400) {
            const float* pa = sHT + tt * 204;
            const float* pb0 = sm + TOK_SW + dd * 204;
            const float* pb1 = sm + TOK_SW + (dd + 50) * 204;
            float acc[4][2];
            #pragma unroll
            for (int i = 0; i < 4; i++) { acc[i][0] = 0.f; acc[i][1] = 0.f; }

            #pragma unroll 2
            for (int j = 0; j < 50; ++j) {
                float4 b0 = *(const float4*)(pb0 + j * 4);
                float4 b1 = *(const float4*)(pb1 + j * 4);
                #pragma unroll
                for (int i = 0; i < 4; ++i) {
                    float4 a = *(const float4*)(pa + i * (8 * 204) + j * 4);
                    acc[i][0] = fmaf(a.x, b0.x, fmaf(a.y, b0.y, fmaf(a.z, b0.z, fmaf(a.w, b0.w, acc[i][0]))));
                    acc[i][1] = fmaf(a.x, b1.x, fmaf(a.y, b1.y, fmaf(a.z, b1.z, fmaf(a.w, b1.w, acc[i][1]))));
                }
            }
            #pragma unroll
            for (int i = 0; i < 4; ++i) {
                int t = tt + 8 * i;
                float c = tanhf(acc[i][0]) * sRT[t * 100 + dd]
                        + tanhf(acc[i][1]) * sRT[t * 100 + dd + 50];
                atomicAdd(&sm[TOK_SE + t], c);
            }
        }
        __syncthreads();

        if (tid < 32) {                               // softmax over 32 triples
            float v = sm[TOK_SE + tid];
            float m = v;
            #pragma unroll
            for (int o = 16; o; o >>= 1) m = fmaxf(m, __shfl_xor_sync(0xffffffffu, m, o));
            float e = expf(v - m);
            float z = e;
            #pragma unroll
            for (int o = 16; o; o >>= 1) z += __shfl_xor_sync(0xffffffffu, z, o);
            sm[TOK_SE + tid] = e / z;
        }
        __syncthreads();

        const int token = tok0 + it;
        const int widx = inputs[token];
        const float2* wsrc = (const float2*)(word_emb + (size_t)widx * 300);
        float2* wdst = (float2*)(g_tin + (size_t)token * 500);
        for (int j = tid; j < 150; j += 512) wdst[j] = wsrc[j];
        if (tid < 200) {
            float ge = 0.f;
            #pragma unroll 8
            for (int t = 0; t < 32; ++t) ge += sm[TOK_SE + t] * sHT[t * 204 + tid];
            int valid = ((int*)(sm + TOK_SVAL))[it];
            g_tin[(size_t)token * 500 + 300 + tid] = valid ? ge : 0.f;
        }
        __syncthreads();
    }
}

// ============================================================================
// K2: g_xp[8192,1024] = g_tin[8192,500] @ w_ih^T + (b_ih + b_hh)
// ============================================================================
__global__ void __launch_bounds__(256)
k_gemm_x(const float* __restrict__ wih, const float* __restrict__ bih,
         const float* __restrict__ bhh)
{
    __shared__ float As[16 * 68];
    __shared__ float Bs[16 * 68];
    const int tid = threadIdx.x;
    const int n0 = blockIdx.x * 64;
    const int m0 = blockIdx.y * 64;
    const int lm = tid >> 2;
    const int lk = (tid & 3) * 4;
    const int ty = tid >> 4;
    const int tx = tid & 15;

    float acc[4][4];
    #pragma unroll
    for (int i = 0; i < 4; i++)
        #pragma unroll
        for (int j = 0; j < 4; j++) acc[i][j] = 0.f;

    const float* arow = g_tin + (size_t)(m0 + lm) * 500;
    const float* brow = wih   + (size_t)(n0 + lm) * 500;

    for (int kt = 0; kt < 32; ++kt) {
        int kb = kt * 16;
        #pragma unroll
        for (int j = 0; j < 4; ++j) {
            int k = kb + lk + j;
            float av = (k < 500) ? arow[k] : 0.f;
            float bv = (k < 500) ? brow[k] : 0.f;
            As[(lk + j) * 68 + lm] = av;
            Bs[(lk + j) * 68 + lm] = bv;
        }
        __syncthreads();
        #pragma unroll
        for (int k = 0; k < 16; ++k) {
            float4 a = *(const float4*)&As[k * 68 + ty * 4];
            float4 b = *(const float4*)&Bs[k * 68 + tx * 4];
            acc[0][0] += a.x*b.x; acc[0][1] += a.x*b.y; acc[0][2] += a.x*b.z; acc[0][3] += a.x*b.w;
            acc[1][0] += a.y*b.x; acc[1][1] += a.y*b.y; acc[1][2] += a.y*b.z; acc[1][3] += a.y*b.w;
            acc[2][0] += a.z*b.x; acc[2][1] += a.z*b.y; acc[2][2] += a.z*b.z; acc[2][3] += a.z*b.w;
            acc[3][0] += a.w*b.x; acc[3][1] += a.w*b.y; acc[3][2] += a.w*b.z; acc[3][3] += a.w*b.w;
        }
        __syncthreads();
    }
    #pragma unroll
    for (int j = 0; j < 4; ++j) {
        int n = n0 + tx * 4 + j;
        float bias = bih[n] + bhh[n];
        #pragma unroll
        for (int i = 0; i < 4; ++i)
            g_xp[(size_t)(m0 + ty * 4 + i) * 1024 + n] = acc[i][j] + bias;
    }
}

// ============================================================================
// K3: persistent LSTM. 128 CTAs x 256 threads. Flag-based sync.
// CTA owns h-cols {2c, 2c+1}. sW[8][256] resident; per step stage h into
// swizzled sH[64][260] (kidx ^ ((b>>3)&1) float4 swizzle, conflict-free).
// ============================================================================
__global__ void __launch_bounds__(256, 1)
k_lstm(const float* __restrict__ whh, const int* __restrict__ lengths)
{
    extern __shared__ float sm[];
    float* sW = sm;            // [8][256]  rows: q*4+g
    float* sH = sm + 2048;     // [64][260] swizzled
    float* sC = sm + 2048 + 64 * 260;   // [64][2]
    int*   sLen = (int*)(sC + 128);     // [64]

    const int tid = threadIdx.x;
    const int cta = blockIdx.x;
    const int hc0 = cta * 2;
    const int ks = tid & 7;
    const int b4 = (tid >> 3) & 15;
    const int q  = tid >> 7;
    const int hc = hc0 + q;

    for (int i = tid; i < 2048; i += 256) {
        int r = i >> 8, k = i & 255;
        int qq = r >> 2, g = r & 3;
        sW[i] = whh[(size_t)(g * 256 + hc0 + qq) * 256 + k];
    }
    if (tid < 128) sC[tid] = 0.f;
    if (tid < 64) sLen[tid] = lengths[tid];
    if (tid < 128) g_h[0][hc0 * 64 + tid] = 0.f;   // rows hc0, hc0+1
    if (tid == 0) g_flag[cta * 32] = 0;
    __threadfence();
    grid_barrier();

    const float* wbase = sW + q * 1024;
    int p = 0;

    for (int s = 0; s < 128; ++s) {
        // prefetch xp for this step (independent of h) to hide under sync
        float xg[16];
        if (ks == 0) {
            #pragma unroll
            for (int bi = 0; bi < 4; ++bi) {
                int b = b4 * 4 + bi;
                const float* xp = g_xp + (size_t)(b * 128 + s) * 1024 + hc;
                xg[bi * 4 + 0] = __ldg(xp);
                xg[bi * 4 + 1] = __ldg(xp + 256);
                xg[bi * 4 + 2] = __ldg(xp + 512);
                xg[bi * 4 + 3] = __ldg(xp + 768);
            }
        }

        if (s > 0 && tid < 128) {
            const int* fl = &g_flag[tid * 32];
            while (ld_acq(fl) < s) { }
        }
        __syncthreads();

        // stage h: g_h[p] is [hc][b]; transpose into swizzled sH[b][k=hc]
        const float* hsrc = g_h[p];
        for (int i = tid; i < 1024; i += 256) {
            int hcc = i >> 4;
            int bq = (i & 15) << 2;
            float4 v = *(const float4*)(hsrc + hcc * 64 + bq);
            int kq = hcc >> 2, kr = hcc & 3;
            #pragma unroll
            for (int r = 0; r < 4; ++r) {
                int b = bq + r;
                float val = (r == 0) ? v.x : (r == 1) ? v.y : (r == 2) ? v.z : v.w;
                sH[b * 260 + ((kq ^ ((b >> 3) & 1)) << 2) + kr] = val;
            }
        }
        __syncthreads();

        float acc[16];
        #pragma unroll
        for (int t = 0; t < 16; ++t) acc[t] = 0.f;

        #pragma unroll
        for (int i = 0; i < 8; ++i) {
            int kidx = ks + (i << 3);
            float4 w0 = *(const float4*)(wbase + 0   + kidx * 4);
            float4 w1 = *(const float4*)(wbase + 256 + kidx * 4);
            float4 w2 = *(const float4*)(wbase + 512 + kidx * 4);
            float4 w3 = *(const float4*)(wbase + 768 + kidx * 4);
            #pragma unroll
            for (int bi = 0; bi < 4; ++bi) {
                int b = b4 * 4 + bi;
                float4 h = *(const float4*)(sH + b * 260 + ((kidx ^ ((b >> 3) & 1)) << 2));
                acc[ 0 + bi] = fmaf(h.x, w0.x, fmaf(h.y, w0.y, fmaf(h.z, w0.z, fmaf(h.w, w0.w, acc[ 0 + bi]))));
                acc[ 4 + bi] = fmaf(h.x, w1.x, fmaf(h.y, w1.y, fmaf(h.z, w1.z, fmaf(h.w, w1.w, acc[ 4 + bi]))));
                acc[ 8 + bi] = fmaf(h.x, w2.x, fmaf(h.y, w2.y, fmaf(h.z, w2.z, fmaf(h.w, w2.w, acc[ 8 + bi]))));
                acc[12 + bi] = fmaf(h.x, w3.x, fmaf(h.y, w3.y, fmaf(h.z, w3.z, fmaf(h.w, w3.w, acc[12 + bi]))));
            }
        }
        #pragma unroll
        for (int off = 1; off < 8; off <<= 1) {
            #pragma unroll
            for (int t = 0; t < 16; ++t)
                acc[t] += __shfl_xor_sync(0xffffffffu, acc[t], off);
        }

        if (ks == 0) {
            #pragma unroll
            for (int bi = 0; bi < 4; ++bi) {
                int b = b4 * 4 + bi;
                float gi = xg[bi * 4 + 0] + acc[ 0 + bi];
                float gf = xg[bi * 4 + 1] + acc[ 4 + bi];
                float gg = xg[bi * 4 + 2] + acc[ 8 + bi];
                float go = xg[bi * 4 + 3] + acc[12 + bi];
                float si = 1.f / (1.f + expf(-gi));
                float sf = 1.f / (1.f + expf(-gf));
                float so = 1.f / (1.f + expf(-go));
                float cn = sf * sC[b * 2 + q] + si * tanhf(gg);
                sC[b * 2 + q] = cn;
                float hv = so * tanhf(cn);
                g_h[p ^ 1][hc * 64 + b] = hv;
                g_outseq[(size_t)(b * 128 + s) * 256 + hc] = (s < sLen[b]) ? hv : 0.f;
            }
        }
        __threadfence();
        __syncthreads();
        if (tid == 0) st_rel(&g_flag[cta * 32], s + 1);
        p ^= 1;
    }
}

// ============================================================================
// K4: attention pool + classifier. out = [ log_probs (64*3) | p (64*128) ]
// ============================================================================
__global__ void __launch_bounds__(256)
k_final(const float* __restrict__ W_att, const float* __restrict__ b_att,
        const float* __restrict__ W_out, const float* __restrict__ b_out,
        float* __restrict__ out)
{
    __shared__ float sLog[128];
    __shared__ float sP[128];
    __shared__ float sEnc[256];
    __shared__ float sZ[3];
    const int tid = threadIdx.x;
    const int b = blockIdx.x;

    if (tid < 128) {
        const float* o = g_outseq + (size_t)(b * 128 + tid) * 256;
        float a = 0.f;
        for (int h = 0; h < 256; ++h) a += o[h] * W_att[h];
        sLog[tid] = a + b_att[0];
    }
    __syncthreads();

    if (tid == 0) {
        float mx = -INFINITY;
        for (int s = 0; s < 128; ++s) {
            float m = (sLog[s] != 0.f) ? 1.f : 0.f;
            mx = fmaxf(mx, sLog[s] * m);
        }
        float den = 0.f;
        for (int s = 0; s < 128; ++s) {
            float m = (sLog[s] != 0.f) ? 1.f : 0.f;
            den += expf(sLog[s] * m - mx);
        }
        float sum2 = 0.f;
        for (int s = 0; s < 128; ++s) {
            float m = (sLog[s] != 0.f) ? 1.f : 0.f;
            float pv = expf(sLog[s] * m - mx) / den * m;
            sP[s] = pv;
            sum2 += pv;
        }
        float inv = 1.f / (sum2 + 1e-13f);
        for (int s = 0; s < 128; ++s) sP[s] *= inv;
    }
    __syncthreads();

    {
        float a = 0.f;
        const float* base = g_outseq + (size_t)b * 128 * 256 + tid;
        for (int s = 0; s < 128; ++s) a += sP[s] * base[s * 256];
        sEnc[tid] = a;
    }
    __syncthreads();

    if (tid < 3) {
        float z = b_out[tid];
        const float* w = W_out + tid * 256;
        for (int h = 0; h < 256; ++h) z += sEnc[h] * w[h];
        sZ[tid] = z;
    }
    __syncthreads();
    if (tid < 3) {
        float mx = fmaxf(sZ[0], fmaxf(sZ[1], sZ[2]));
        float lse = mx + logf(expf(sZ[0] - mx) + expf(sZ[1] - mx) + expf(sZ[2] - mx));
        out[b * 3 + tid] = sZ[tid] - lse;
    }
    if (tid < 128) out[192 + b * 128 + tid] = sP[tid];
}

// ============================================================================
extern "C" void kernel_launch(void* const* d_in, const int* in_sizes, int n_in,
                              void* d_out, int out_size)
{
    const int*   inputs   = (const int*)d_in[0];
    const int*   triples  = (const int*)d_in[1];
    const int*   lengths  = (const int*)d_in[2];
    const int*   id2      = (const int*)d_in[3];
    const float* word_emb = (const float*)d_in[4];
    const float* ent_emb  = (const float*)d_in[5];
    const float* rel_emb  = (const float*)d_in[6];
    const float* W_ent    = (const float*)d_in[7];
    const float* w_ih     = (const float*)d_in[8];
    const float* w_hh     = (const float*)d_in[9];
    const float* b_ih     = (const float*)d_in[10];
    const float* b_hh     = (const float*)d_in[11];
    const float* W_att    = (const float*)d_in[12];
    const float* b_att    = (const float*)d_in[13];
    const float* W_out    = (const float*)d_in[14];
    const float* b_out    = (const float*)d_in[15];
    float* out = (float*)d_out;

    static int inited = 0;
    if (!inited) {
        cudaFuncSetAttribute(k_token, cudaFuncAttributeMaxDynamicSharedMemorySize, TOK_SMEM);
        cudaFuncSetAttribute(k_lstm,  cudaFuncAttributeMaxDynamicSharedMemorySize,
                             (2048 + 64 * 260 + 128 + 64) * 4);
        inited = 1;
    }

    k_tanh_rel<<<(50000 + 255) / 256, 256>>>(rel_emb);
    k_token<<<512, 512, TOK_SMEM>>>(inputs, triples, id2, word_emb, ent_emb, W_ent);
    dim3 g2(16, 128);
    k_gemm_x<<<g2, 256>>>(w_ih, b_ih, b_hh);
    k_lstm<<<NB_LSTM, 256, (2048 + 64 * 260 + 128 + 64) * 4>>>(w_hh, lengths);
    k_final<<<64, 256>>>(W_att, b_att, W_out, b_out, out);
}

// round 4
// speedup vs baseline: 1.7496x; 1.1011x over previous
#include <cuda_runtime.h>
#include <math.h>
#include <stdint.h>

// ---------------- device scratch ----------------
__device__ __align__(16) float g_trel[500 * 100];
__device__ __align__(16) float g_tin[8192 * 500];
__device__ __align__(16) float g_xp[8192 * 1024];
__device__ __align__(16) float g_outseq[8192 * 256];

// ---------------- helpers ----------------
__device__ __forceinline__ unsigned smem_u32(const void* p) {
    return (unsigned)__cvta_generic_to_shared(p);
}
__device__ __forceinline__ void cpa16(unsigned dst, const void* src) {
    asm volatile("cp.async.cg.shared.global [%0], [%1], 16;\n" :: "r"(dst), "l"(src));
}
#define CPA_COMMIT() asm volatile("cp.async.commit_group;\n")
template <int N> __device__ __forceinline__ void cpa_wait() {
    asm volatile("cp.async.wait_group %0;\n" :: "n"(N));
}
#define FMA2(acc, h, w) \
    asm("fma.rn.f32x2 %0, %1, %2, %0;" : "+l"(acc) : "l"(h), "l"(w))
#define PACK2(dst, v) \
    asm("mov.b64 %0, {%1, %1};" : "=l"(dst) : "f"(v))
#define UNPACK2(lo, hi, src) \
    asm("mov.b64 {%0, %1}, %2;" : "=f"(lo), "=f"(hi) : "l"(src))

// ============================================================================
// K0: precompute tanh(rel_emb)
// ============================================================================
__global__ void k_tanh_rel(const float* __restrict__ rel) {
    int i = blockIdx.x * 256 + threadIdx.x;
    if (i < 500 * 100) g_trel[i] = tanhf(rel[i]);
}

// ============================================================================
// K1: graph attention. 512 CTAs x 512 threads, 16 tokens per CTA.
// ============================================================================
#define TOK_SW    0
#define TOK_SHT   20400
#define TOK_SRT   33456
#define TOK_SE    39856
#define TOK_SIDX  39888
#define TOK_SVAL  41424
#define TOK_SPART 41440
#define TOK_SMEM  ((41440 + 32 * 52) * 4)

__device__ __forceinline__ void tok_stage(float* sm, int buf, int it,
                                          const float* ent_emb) {
    const int* idx = (const int*)(sm + TOK_SIDX) + it * 96;
    float* sHT = sm + TOK_SHT + buf * 32 * 204;
    float* sRT = sm + TOK_SRT + buf * 32 * 100;
    for (int i = threadIdx.x; i < 2400; i += 512) {
        if (i < 1600) {
            int t = i / 50, j = i - t * 50;
            int ent = (j < 25) ? idx[t * 3] : idx[t * 3 + 1];
            int jj = (j < 25) ? j : (j - 25);
            int dstf = t * 204 + ((j < 25) ? (j * 4) : (100 + jj * 4));
            cpa16(smem_u32(sHT + dstf), ent_emb + (size_t)ent * 100 + jj * 4);
        } else {
            int r = i - 1600;
            int t = r / 25, j = r - t * 25;
            int rl = idx[t * 3 + 2];
            cpa16(smem_u32(sRT + t * 100 + j * 4), g_trel + rl * 100 + j * 4);
        }
    }
}

__global__ void __launch_bounds__(512, 1)
k_token(const int* __restrict__ inputs, const int* __restrict__ triples,
        const int* __restrict__ id2, const float* __restrict__ word_emb,
        const float* __restrict__ ent_emb, const float* __restrict__ W_ent)
{
    extern __shared__ float sm[];
    const int tid = threadIdx.x;
    const int tok0 = blockIdx.x * 16;

    for (int i = tid; i < 384; i += 512)
        cpa16(smem_u32(sm + TOK_SIDX) + i * 16, triples + (size_t)tok0 * 96 + i * 4);
    for (int i = tid; i < 5000; i += 512) {
        int d = i / 50, j = i - d * 50;
        cpa16(smem_u32(sm + TOK_SW + d * 204 + j * 4), W_ent + d * 200 + j * 4);
    }
    CPA_COMMIT();
    cpa_wait<0>();
    __syncthreads();

    {
        int it = tid >> 5, lane = tid & 31;
        int v = id2[(size_t)(tok0 + it) * 32 + lane];
        unsigned m = __ballot_sync(0xffffffffu, v != -1);
        if (lane == 0) ((int*)(sm + TOK_SVAL))[it] = (m != 0u);
    }

    tok_stage(sm, 0, 0, ent_emb);
    CPA_COMMIT();

    const int tt = tid & 7;
    const int dd = tid >> 3;

    for (int it = 0; it < 16; ++it) {
        const int buf = it & 1;
        if (it < 15) {
            tok_stage(sm, buf ^ 1, it + 1, ent_emb);
            CPA_COMMIT();
            cpa_wait<1>();
        } else {
            cpa_wait<0>();
        }
        __syncthreads();

        const float* sHT = sm + TOK_SHT + buf * 32 * 204;
        const float* sRT = sm + TOK_SRT + buf * 32 * 100;

        if (tid < 400) {
            const float* pa = sHT + tt * 204;
            const float* pb0 = sm + TOK_SW + dd * 204;
            const float* pb1 = sm + TOK_SW + (dd + 50) * 204;
            float acc[4][2];
            #pragma unroll
            for (int i = 0; i < 4; i++) { acc[i][0] = 0.f; acc[i][1] = 0.f; }

            #pragma unroll 2
            for (int j = 0; j < 50; ++j) {
                float4 b0 = *(const float4*)(pb0 + j * 4);
                float4 b1 = *(const float4*)(pb1 + j * 4);
                #pragma unroll
                for (int i = 0; i < 4; ++i) {
                    float4 a = *(const float4*)(pa + i * (8 * 204) + j * 4);
                    acc[i][0] = fmaf(a.x, b0.x, fmaf(a.y, b0.y, fmaf(a.z, b0.z, fmaf(a.w, b0.w, acc[i][0]))));
                    acc[i][1] = fmaf(a.x, b1.x, fmaf(a.y, b1.y, fmaf(a.z, b1.z, fmaf(a.w, b1.w, acc[i][1]))));
                }
            }
            #pragma unroll
            for (int i = 0; i < 4; ++i) {
                int t = tt + 8 * i;
                float c = tanhf(acc[i][0]) * sRT[t * 100 + dd]
                        + tanhf(acc[i][1]) * sRT[t * 100 + dd + 50];
                sm[TOK_SPART + t * 52 + dd] = c;      // partial, no atomics
            }
        }
        __syncthreads();

        // reduce partials: 512 threads = 32 groups of 16
        {
            int t = tid >> 4, l = tid & 15;
            float v = sm[TOK_SPART + t * 52 + l]
                    + sm[TOK_SPART + t * 52 + l + 16]
                    + sm[TOK_SPART + t * 52 + l + 32];
            if (l < 2) v += sm[TOK_SPART + t * 52 + l + 48];
            #pragma unroll
            for (int o = 8; o; o >>= 1) v += __shfl_xor_sync(0xffffffffu, v, o);
            if (l == 0) sm[TOK_SE + t] = v;
        }
        __syncthreads();

        if (tid < 32) {
            float v = sm[TOK_SE + tid];
            float m = v;
            #pragma unroll
            for (int o = 16; o; o >>= 1) m = fmaxf(m, __shfl_xor_sync(0xffffffffu, m, o));
            float e = expf(v - m);
            float z = e;
            #pragma unroll
            for (int o = 16; o; o >>= 1) z += __shfl_xor_sync(0xffffffffu, z, o);
            sm[TOK_SE + tid] = e / z;
        }
        __syncthreads();

        const int token = tok0 + it;
        const int widx = inputs[token];
        const float2* wsrc = (const float2*)(word_emb + (size_t)widx * 300);
        float2* wdst = (float2*)(g_tin + (size_t)token * 500);
        for (int j = tid; j < 150; j += 512) wdst[j] = wsrc[j];
        if (tid < 200) {
            float ge = 0.f;
            #pragma unroll 8
            for (int t = 0; t < 32; ++t) ge += sm[TOK_SE + t] * sHT[t * 204 + tid];
            int valid = ((int*)(sm + TOK_SVAL))[it];
            g_tin[(size_t)token * 500 + 300 + tid] = valid ? ge : 0.f;
        }
        __syncthreads();
    }
}

// ============================================================================
// K2: g_xp[8192,1024] = g_tin[8192,500] @ w_ih^T + (b_ih + b_hh)
// ============================================================================
__global__ void __launch_bounds__(256)
k_gemm_x(const float* __restrict__ wih, const float* __restrict__ bih,
         const float* __restrict__ bhh)
{
    __shared__ float As[16 * 68];
    __shared__ float Bs[16 * 68];
    const int tid = threadIdx.x;
    const int n0 = blockIdx.x * 64;
    const int m0 = blockIdx.y * 64;
    const int lm = tid >> 2;
    const int lk = (tid & 3) * 4;
    const int ty = tid >> 4;
    const int tx = tid & 15;

    float acc[4][4];
    #pragma unroll
    for (int i = 0; i < 4; i++)
        #pragma unroll
        for (int j = 0; j < 4; j++) acc[i][j] = 0.f;

    const float* arow = g_tin + (size_t)(m0 + lm) * 500;
    const float* brow = wih   + (size_t)(n0 + lm) * 500;

    for (int kt = 0; kt < 32; ++kt) {
        int kb = kt * 16;
        #pragma unroll
        for (int j = 0; j < 4; ++j) {
            int k = kb + lk + j;
            float av = (k < 500) ? arow[k] : 0.f;
            float bv = (k < 500) ? brow[k] : 0.f;
            As[(lk + j) * 68 + lm] = av;
            Bs[(lk + j) * 68 + lm] = bv;
        }
        __syncthreads();
        #pragma unroll
        for (int k = 0; k < 16; ++k) {
            float4 a = *(const float4*)&As[k * 68 + ty * 4];
            float4 b = *(const float4*)&Bs[k * 68 + tx * 4];
            acc[0][0] += a.x*b.x; acc[0][1] += a.x*b.y; acc[0][2] += a.x*b.z; acc[0][3] += a.x*b.w;
            acc[1][0] += a.y*b.x; acc[1][1] += a.y*b.y; acc[1][2] += a.y*b.z; acc[1][3] += a.y*b.w;
            acc[2][0] += a.z*b.x; acc[2][1] += a.z*b.y; acc[2][2] += a.z*b.z; acc[2][3] += a.z*b.w;
            acc[3][0] += a.w*b.x; acc[3][1] += a.w*b.y; acc[3][2] += a.w*b.z; acc[3][3] += a.w*b.w;
        }
        __syncthreads();
    }
    #pragma unroll
    for (int j = 0; j < 4; ++j) {
        int n = n0 + tx * 4 + j;
        float bias = bih[n] + bhh[n];
        #pragma unroll
        for (int i = 0; i < 4; ++i)
            g_xp[(size_t)(m0 + ty * 4 + i) * 1024 + n] = acc[i][j] + bias;
    }
}

// ============================================================================
// K3: cluster LSTM. 16 independent clusters of 8 CTAs; cluster owns 4 batches.
// CTA rank r: 512 threads; w_hh slice (hc in [32r,32r+32), 4 gates, k-split 8)
// resident in REGISTERS (64/thread). h in smem, exchanged via DSMEM multicast
// stores + cluster.sync each step. Packed f32x2 FMA (batch pairs).
//
// smem h layout (per buffer, per batch-pair bp): float idx
//   L = k*2 + (b&1); quad Q = k>>1; Q' = Q ^ ((Q>>4)&7);
//   idx = Q'*4 + 2*(k&1) + (b&1)          (512 floats + pad)
// Reader (ks, j): Q' = (ks*16+j)^ks -> 8 distinct bank groups, conflict-free.
// ============================================================================
__device__ __forceinline__ int h_sw_idx(int b, int k) {
    int Q = k >> 1;
    int Qp = Q ^ ((Q >> 4) & 7);
    return (Qp << 2) + ((k & 1) << 1) + (b & 1);
}

__global__ void __launch_bounds__(512, 1) __cluster_dims__(8, 1, 1)
k_lstm(const float* __restrict__ whh, const int* __restrict__ lengths)
{
    __shared__ __align__(16) float sH[2][2][520];   // [buf][bp][...]
    __shared__ float sGate[4][4][33];               // [gate][b][hc]

    const int tid  = threadIdx.x;
    const int rank = blockIdx.x & 7;
    const int cid  = blockIdx.x >> 3;
    const int b0g  = cid * 4;

    const int lane = tid & 31;
    const int ks   = lane & 7;          // k-split
    const int hcq  = lane >> 3;         // 0..3
    const int warp = tid >> 5;
    const int hc_h = warp & 7;
    const int gh   = warp >> 3;         // gate half: 0->(i,f) 1->(g,o)
    const int hc_l = hc_h * 4 + hcq;
    const int hc_g = rank * 32 + hc_l;

    // ---- persistent weights in registers ----
    float wA[32], wB[32];
    {
        const float4* pa = (const float4*)(whh + ((size_t)(gh * 2    ) * 256 + hc_g) * 256 + ks * 32);
        const float4* pb = (const float4*)(whh + ((size_t)(gh * 2 + 1) * 256 + hc_g) * 256 + ks * 32);
        #pragma unroll
        for (int j = 0; j < 8; ++j) {
            float4 a = __ldg(pa + j);
            float4 b = __ldg(pb + j);
            wA[j*4+0]=a.x; wA[j*4+1]=a.y; wA[j*4+2]=a.z; wA[j*4+3]=a.w;
            wB[j*4+0]=b.x; wB[j*4+1]=b.y; wB[j*4+2]=b.z; wB[j*4+3]=b.w;
        }
    }

    for (int i = tid; i < 2 * 2 * 520; i += 512) ((float*)sH)[i] = 0.f;

    // activation-thread state (tid < 128: b_l = tid>>5, hc = tid&31)
    float cst = 0.f;
    int mylen = 0;
    const int abl = tid >> 5;           // batch (valid tid<128)
    const int ahc = tid & 31;           // local hc (valid tid<128)
    if (tid < 128) mylen = lengths[b0g + abl];

    __syncthreads();
    asm volatile("barrier.cluster.arrive.aligned;" ::: "memory");
    asm volatile("barrier.cluster.wait.aligned;" ::: "memory");

    int p = 0;
    for (int s = 0; s < 128; ++s) {
        // (a) prefetch x-projection gates (hides under compute)
        float xg0 = 0.f, xg1 = 0.f, xg2 = 0.f, xg3 = 0.f;
        if (tid < 128) {
            const float* xp = g_xp + ((size_t)((b0g + abl) * 128 + s)) * 1024 + rank * 32 + ahc;
            xg0 = __ldg(xp);
            xg1 = __ldg(xp + 256);
            xg2 = __ldg(xp + 512);
            xg3 = __ldg(xp + 768);
        }

        // (b) packed GEMV over own smem h
        unsigned long long aA0 = 0ull, aA1 = 0ull, aB0 = 0ull, aB1 = 0ull;
        #pragma unroll
        for (int j = 0; j < 16; ++j) {
            int Qp = (ks * 16 + j) ^ ks;
            ulonglong2 h0 = *(const ulonglong2*)&sH[p][0][Qp << 2];
            ulonglong2 h1 = *(const ulonglong2*)&sH[p][1][Qp << 2];
            unsigned long long wa0, wa1, wb0, wb1;
            PACK2(wa0, wA[2*j]); PACK2(wa1, wA[2*j+1]);
            PACK2(wb0, wB[2*j]); PACK2(wb1, wB[2*j+1]);
            FMA2(aA0, h0.x, wa0); FMA2(aA0, h0.y, wa1);
            FMA2(aA1, h1.x, wa0); FMA2(aA1, h1.y, wa1);
            FMA2(aB0, h0.x, wb0); FMA2(aB0, h0.y, wb1);
            FMA2(aB1, h1.x, wb0); FMA2(aB1, h1.y, wb1);
        }
        float rA0, rA1, rA2, rA3, rB0, rB1, rB2, rB3;
        UNPACK2(rA0, rA1, aA0); UNPACK2(rA2, rA3, aA1);
        UNPACK2(rB0, rB1, aB0); UNPACK2(rB2, rB3, aB1);
        #pragma unroll
        for (int o = 1; o < 8; o <<= 1) {
            rA0 += __shfl_xor_sync(0xffffffffu, rA0, o);
            rA1 += __shfl_xor_sync(0xffffffffu, rA1, o);
            rA2 += __shfl_xor_sync(0xffffffffu, rA2, o);
            rA3 += __shfl_xor_sync(0xffffffffu, rA3, o);
            rB0 += __shfl_xor_sync(0xffffffffu, rB0, o);
            rB1 += __shfl_xor_sync(0xffffffffu, rB1, o);
            rB2 += __shfl_xor_sync(0xffffffffu, rB2, o);
            rB3 += __shfl_xor_sync(0xffffffffu, rB3, o);
        }
        if (ks == 0) {
            int gA = gh * 2, gB = gh * 2 + 1;
            sGate[gA][0][hc_l] = rA0; sGate[gA][1][hc_l] = rA1;
            sGate[gA][2][hc_l] = rA2; sGate[gA][3][hc_l] = rA3;
            sGate[gB][0][hc_l] = rB0; sGate[gB][1][hc_l] = rB1;
            sGate[gB][2][hc_l] = rB2; sGate[gB][3][hc_l] = rB3;
        }
        __syncthreads();

        // (e) activation + DSMEM broadcast of new h to all 8 ranks
        if (tid < 128) {
            float gi = xg0 + sGate[0][abl][ahc];
            float gf = xg1 + sGate[1][abl][ahc];
            float gg = xg2 + sGate[2][abl][ahc];
            float go = xg3 + sGate[3][abl][ahc];
            float si = 1.f / (1.f + expf(-gi));
            float sf = 1.f / (1.f + expf(-gf));
            float so = 1.f / (1.f + expf(-go));
            cst = sf * cst + si * tanhf(gg);
            float hv = so * tanhf(cst);
            g_outseq[((size_t)((b0g + abl) * 128 + s)) * 256 + rank * 32 + ahc] =
                (s < mylen) ? hv : 0.f;
            int idx = h_sw_idx(abl, rank * 32 + ahc);
            unsigned laddr = smem_u32(&sH[p ^ 1][abl >> 1][idx]);
            #pragma unroll
            for (int r = 0; r < 8; ++r) {
                unsigned raddr;
                asm("mapa.shared::cluster.u32 %0, %1, %2;" : "=r"(raddr) : "r"(laddr), "r"(r));
                asm volatile("st.shared::cluster.f32 [%0], %1;" :: "r"(raddr), "f"(hv));
            }
        }
        asm volatile("barrier.cluster.arrive.aligned;" ::: "memory");
        asm volatile("barrier.cluster.wait.aligned;" ::: "memory");
        p ^= 1;
    }
}

// ============================================================================
// K4: attention pool + classifier. out = [ log_probs (64*3) | p (64*128) ]
// ============================================================================
__global__ void __launch_bounds__(256)
k_final(const float* __restrict__ W_att, const float* __restrict__ b_att,
        const float* __restrict__ W_out, const float* __restrict__ b_out,
        float* __restrict__ out)
{
    __shared__ float sLog[128];
    __shared__ float sP[128];
    __shared__ float sEnc[256];
    __shared__ float sZ[3];
    const int tid = threadIdx.x;
    const int b = blockIdx.x;

    if (tid < 128) {
        const float* o = g_outseq + (size_t)(b * 128 + tid) * 256;
        float a = 0.f;
        for (int h = 0; h < 256; ++h) a += o[h] * W_att[h];
        sLog[tid] = a + b_att[0];
    }
    __syncthreads();

    if (tid == 0) {
        float mx = -INFINITY;
        for (int s = 0; s < 128; ++s) {
            float m = (sLog[s] != 0.f) ? 1.f : 0.f;
            mx = fmaxf(mx, sLog[s] * m);
        }
        float den = 0.f;
        for (int s = 0; s < 128; ++s) {
            float m = (sLog[s] != 0.f) ? 1.f : 0.f;
            den += expf(sLog[s] * m - mx);
        }
        float sum2 = 0.f;
        for (int s = 0; s < 128; ++s) {
            float m = (sLog[s] != 0.f) ? 1.f : 0.f;
            float pv = expf(sLog[s] * m - mx) / den * m;
            sP[s] = pv;
            sum2 += pv;
        }
        float inv = 1.f / (sum2 + 1e-13f);
        for (int s = 0; s < 128; ++s) sP[s] *= inv;
    }
    __syncthreads();

    {
        float a = 0.f;
        const float* base = g_outseq + (size_t)b * 128 * 256 + tid;
        for (int s = 0; s < 128; ++s) a += sP[s] * base[s * 256];
        sEnc[tid] = a;
    }
    __syncthreads();

    if (tid < 3) {
        float z = b_out[tid];
        const float* w = W_out + tid * 256;
        for (int h = 0; h < 256; ++h) z += sEnc[h] * w[h];
        sZ[tid] = z;
    }
    __syncthreads();
    if (tid < 3) {
        float mx = fmaxf(sZ[0], fmaxf(sZ[1], sZ[2]));
        float lse = mx + logf(expf(sZ[0] - mx) + expf(sZ[1] - mx) + expf(sZ[2] - mx));
        out[b * 3 + tid] = sZ[tid] - lse;
    }
    if (tid < 128) out[192 + b * 128 + tid] = sP[tid];
}

// ============================================================================
extern "C" void kernel_launch(void* const* d_in, const int* in_sizes, int n_in,
                              void* d_out, int out_size)
{
    const int*   inputs   = (const int*)d_in[0];
    const int*   triples  = (const int*)d_in[1];
    const int*   lengths  = (const int*)d_in[2];
    const int*   id2      = (const int*)d_in[3];
    const float* word_emb = (const float*)d_in[4];
    const float* ent_emb  = (const float*)d_in[5];
    const float* rel_emb  = (const float*)d_in[6];
    const float* W_ent    = (const float*)d_in[7];
    const float* w_ih     = (const float*)d_in[8];
    const float* w_hh     = (const float*)d_in[9];
    const float* b_ih     = (const float*)d_in[10];
    const float* b_hh     = (const float*)d_in[11];
    const float* W_att    = (const float*)d_in[12];
    const float* b_att    = (const float*)d_in[13];
    const float* W_out    = (const float*)d_in[14];
    const float* b_out    = (const float*)d_in[15];
    float* out = (float*)d_out;

    cudaFuncSetAttribute(k_token, cudaFuncAttributeMaxDynamicSharedMemorySize, TOK_SMEM);

    k_tanh_rel<<<(50000 + 255) / 256, 256>>>(rel_emb);
    k_token<<<512, 512, TOK_SMEM>>>(inputs, triples, id2, word_emb, ent_emb, W_ent);
    dim3 g2(16, 128);
    k_gemm_x<<<g2, 256>>>(w_ih, b_ih, b_hh);
    k_lstm<<<128, 512>>>(w_hh, lengths);
    k_final<<<64, 256>>>(W_att, b_att, W_out, b_out, out);
}